// round 1
// baseline (speedup 1.0000x reference)
#include <cuda_runtime.h>

#define NEGV (-1000000000.0f)

// B=2 S=2048 D=1024 H=16 A=64
// qkv row stride = 3*H*A = 3072; M = B*S = 4096

__device__ float g_qkv[(size_t)4096 * 3072];  // 48 MB scratch
__device__ float g_ctx[(size_t)4096 * 1024];  // 16 MB scratch

// ---------------------------------------------------------------------------
// SGEMM: C[M,N] = A[M,K] * B[K,N] (+ bias[N] if bias != nullptr)
// 128x128 block, BK=8, 256 threads, 8x8 microtile (4+4 split both dims)
// ---------------------------------------------------------------------------
__global__ __launch_bounds__(256) void sgemm128(
    const float* __restrict__ A, const float* __restrict__ B,
    const float* __restrict__ bias, float* __restrict__ C,
    int M, int N, int K)
{
    __shared__ float As[8][128];
    __shared__ float Bsm[8][128];

    const int tid = threadIdx.x;
    const int bx = blockIdx.x, by = blockIdx.y;

    const float* Ab = A + (size_t)by * 128 * K;
    const float* Bb = B + (size_t)bx * 128;

    const int arow = tid >> 1, acol = (tid & 1) * 4;
    const int brow = tid >> 5, bcol = (tid & 31) * 4;
    const int tx = tid & 15, ty = tid >> 4;

    float acc[8][8];
#pragma unroll
    for (int i = 0; i < 8; i++)
#pragma unroll
        for (int j = 0; j < 8; j++) acc[i][j] = 0.0f;

    float4 aR = *(const float4*)(Ab + (size_t)arow * K + acol);
    float4 bR = *(const float4*)(Bb + (size_t)brow * N + bcol);

    const int nt = K >> 3;
    for (int t = 0;;) {
        As[acol + 0][arow] = aR.x;
        As[acol + 1][arow] = aR.y;
        As[acol + 2][arow] = aR.z;
        As[acol + 3][arow] = aR.w;
        *(float4*)&Bsm[brow][bcol] = bR;
        __syncthreads();
        t++;
        if (t < nt) {
            aR = *(const float4*)(Ab + (size_t)arow * K + t * 8 + acol);
            bR = *(const float4*)(Bb + (size_t)(t * 8 + brow) * N + bcol);
        }
#pragma unroll
        for (int k = 0; k < 8; k++) {
            float af[8], bf[8];
            *(float4*)&af[0] = *(const float4*)&As[k][ty * 4];
            *(float4*)&af[4] = *(const float4*)&As[k][64 + ty * 4];
            *(float4*)&bf[0] = *(const float4*)&Bsm[k][tx * 4];
            *(float4*)&bf[4] = *(const float4*)&Bsm[k][64 + tx * 4];
#pragma unroll
            for (int i = 0; i < 8; i++)
#pragma unroll
                for (int j = 0; j < 8; j++)
                    acc[i][j] += af[i] * bf[j];
        }
        if (t == nt) break;
        __syncthreads();
    }

    float bv[8];
#pragma unroll
    for (int j = 0; j < 8; j++) bv[j] = 0.0f;
    if (bias) {
#pragma unroll
        for (int j = 0; j < 4; j++) {
            bv[j]     = bias[bx * 128 + tx * 4 + j];
            bv[j + 4] = bias[bx * 128 + 64 + tx * 4 + j];
        }
    }

#pragma unroll
    for (int i = 0; i < 8; i++) {
        int lr = (i < 4) ? (ty * 4 + i) : (64 + ty * 4 + (i - 4));
        float* crow = C + (size_t)(by * 128 + lr) * N + bx * 128;
        float4 o0, o1;
        o0.x = acc[i][0] + bv[0]; o0.y = acc[i][1] + bv[1];
        o0.z = acc[i][2] + bv[2]; o0.w = acc[i][3] + bv[3];
        o1.x = acc[i][4] + bv[4]; o1.y = acc[i][5] + bv[5];
        o1.z = acc[i][6] + bv[6]; o1.w = acc[i][7] + bv[7];
        *(float4*)(crow + tx * 4)      = o0;
        *(float4*)(crow + 64 + tx * 4) = o1;
    }
}

// ---------------------------------------------------------------------------
// Fused attention: per block = one (b, h, 128-row q tile).
// Flash-style online softmax over 32 key tiles of 64.
// Thread layout: rg = tid>>3 (row group, 4 rows), cg = tid&7 (8 cols).
// Scores live in registers (4x8), row reductions via shfl among 8 lanes.
// ---------------------------------------------------------------------------
__global__ __launch_bounds__(256) void attn_kernel(
    const float* __restrict__ qkv, const int* __restrict__ mask,
    float* __restrict__ ctx)
{
    extern __shared__ float sm[];
    float* Qs = sm;            // [128][68]  (stride 68, 16B aligned rows)
    float* Ks = sm + 8704;     // [64][64]   XOR-swizzled float4 layout
    float* Vs = Ks + 4096;     // [64][64]
    float* Ps = Vs + 4096;     // [128][65]
    float* Mk = Ps + 8320;     // [64]

    const int tid = threadIdx.x;
    const int q0 = blockIdx.x * 128;
    const int h  = blockIdx.y;
    const int b  = blockIdx.z;
    const int rg = tid >> 3;
    const int cg = tid & 7;
    const int r0 = rg * 4;

    const size_t baseRow = (size_t)b * 2048;

    // Load Q tile [128 x 64] into smem (row-major, stride 68)
#pragma unroll
    for (int i = 0; i < 8; i++) {
        int lin = tid + 256 * i;
        int r = lin >> 4, a4 = lin & 15;
        float4 v = *(const float4*)(qkv + (baseRow + q0 + r) * 3072 + h * 64 + a4 * 4);
        *(float4*)&Qs[r * 68 + a4 * 4] = v;
    }

    float O[4][8];
    float mrow[4], lrow[4];
#pragma unroll
    for (int i = 0; i < 4; i++) {
        mrow[i] = -1e30f;
        lrow[i] = 0.0f;
#pragma unroll
        for (int j = 0; j < 8; j++) O[i][j] = 0.0f;
    }

    for (int t = 0; t < 32; t++) {
        const int k0 = t * 64;
        __syncthreads();  // previous PV phase done before overwriting K/V/Ps

        // Load K (swizzled) and V tiles [64 x 64]
#pragma unroll
        for (int i = 0; i < 4; i++) {
            int lin = tid + 256 * i;
            int k = lin >> 4, a4 = lin & 15;
            const float* src = qkv + (baseRow + k0 + k) * 3072 + h * 64;
            float4 kv = *(const float4*)(src + 1024 + a4 * 4);
            *(float4*)&Ks[(k * 16 + (a4 ^ ((k >> 3) & 7))) * 4] = kv;
            float4 vv = *(const float4*)(src + 2048 + a4 * 4);
            *(float4*)&Vs[k * 64 + a4 * 4] = vv;
        }
        if (tid < 64) Mk[tid] = (float)mask[b * 2048 + k0 + tid];
        __syncthreads();

        // Phase A: S = Q * K^T  (4 rows x 8 keys per thread)
        float sv[4][8];
#pragma unroll
        for (int i = 0; i < 4; i++)
#pragma unroll
            for (int j = 0; j < 8; j++) sv[i][j] = 0.0f;

#pragma unroll 2
        for (int a4 = 0; a4 < 16; a4++) {
            float4 qf[4];
#pragma unroll
            for (int i = 0; i < 4; i++)
                qf[i] = *(const float4*)&Qs[(r0 + i) * 68 + a4 * 4];
#pragma unroll
            for (int j = 0; j < 8; j++) {
                int c = cg * 8 + j;
                float4 kf = *(const float4*)&Ks[(c * 16 + (a4 ^ ((c >> 3) & 7))) * 4];
#pragma unroll
                for (int i = 0; i < 4; i++)
                    sv[i][j] += qf[i].x * kf.x + qf[i].y * kf.y +
                                qf[i].z * kf.z + qf[i].w * kf.w;
            }
        }

        // Mask + online softmax update
#pragma unroll
        for (int i = 0; i < 4; i++) {
            float mx = -1e30f;
#pragma unroll
            for (int j = 0; j < 8; j++) {
                float x = sv[i][j] * 0.125f;
                x = (Mk[cg * 8 + j] == 0.0f) ? NEGV : x;
                sv[i][j] = x;
                mx = fmaxf(mx, x);
            }
            mx = fmaxf(mx, __shfl_xor_sync(0xffffffffu, mx, 1));
            mx = fmaxf(mx, __shfl_xor_sync(0xffffffffu, mx, 2));
            mx = fmaxf(mx, __shfl_xor_sync(0xffffffffu, mx, 4));
            float mnew = fmaxf(mrow[i], mx);
            float alpha = __expf(mrow[i] - mnew);
            float ps = 0.0f;
#pragma unroll
            for (int j = 0; j < 8; j++) {
                float p = __expf(sv[i][j] - mnew);
                sv[i][j] = p;
                ps += p;
            }
            ps += __shfl_xor_sync(0xffffffffu, ps, 1);
            ps += __shfl_xor_sync(0xffffffffu, ps, 2);
            ps += __shfl_xor_sync(0xffffffffu, ps, 4);
            lrow[i] = lrow[i] * alpha + ps;
            mrow[i] = mnew;
#pragma unroll
            for (int j = 0; j < 8; j++) O[i][j] *= alpha;
#pragma unroll
            for (int j = 0; j < 8; j++)
                Ps[(r0 + i) * 65 + cg * 8 + j] = sv[i][j];
        }
        // Rows r0..r0+3 of Ps are produced only by the 8 lanes of this warp
        // that share rg, and consumed by the same lanes -> warp sync suffices.
        __syncwarp();

        // Phase B: O += P * V  (4 rows x 8 d-cols per thread)
#pragma unroll 4
        for (int k = 0; k < 64; k++) {
            float pv[4];
#pragma unroll
            for (int i = 0; i < 4; i++) pv[i] = Ps[(r0 + i) * 65 + k];
            float vv[8];
            *(float4*)&vv[0] = *(const float4*)&Vs[k * 64 + cg * 8];
            *(float4*)&vv[4] = *(const float4*)&Vs[k * 64 + cg * 8 + 4];
#pragma unroll
            for (int i = 0; i < 4; i++)
#pragma unroll
                for (int j = 0; j < 8; j++)
                    O[i][j] += pv[i] * vv[j];
        }
    }

    // Epilogue: normalize and write ctx[b, s, h*64 + d]
#pragma unroll
    for (int i = 0; i < 4; i++) {
        float inv = 1.0f / lrow[i];
        float* dst = ctx + (baseRow + q0 + r0 + i) * 1024 + h * 64 + cg * 8;
        float4 o0, o1;
        o0.x = O[i][0] * inv; o0.y = O[i][1] * inv;
        o0.z = O[i][2] * inv; o0.w = O[i][3] * inv;
        o1.x = O[i][4] * inv; o1.y = O[i][5] * inv;
        o1.z = O[i][6] * inv; o1.w = O[i][7] * inv;
        *(float4*)&dst[0] = o0;
        *(float4*)&dst[4] = o1;
    }
}

// ---------------------------------------------------------------------------
extern "C" void kernel_launch(void* const* d_in, const int* in_sizes, int n_in,
                              void* d_out, int out_size)
{
    const float* qs   = (const float*)d_in[0];
    const int*   mask = (const int*)d_in[1];
    const float* Wqkv = (const float*)d_in[2];
    const float* Wout = (const float*)d_in[3];
    const float* bout = (const float*)d_in[4];
    float* out = (float*)d_out;

    float *qkvP, *ctxP;
    cudaGetSymbolAddress((void**)&qkvP, g_qkv);
    cudaGetSymbolAddress((void**)&ctxP, g_ctx);

    const int attnSmem = 25280 * 4;  // 101120 bytes
    cudaFuncSetAttribute(attn_kernel,
                         cudaFuncAttributeMaxDynamicSharedMemorySize, attnSmem);

    // 1) qkv = qs @ Wqkv              [4096,1024] x [1024,3072]
    sgemm128<<<dim3(24, 32), 256>>>(qs, Wqkv, nullptr, qkvP, 4096, 3072, 1024);

    // 2) fused masked attention -> ctx [B,S,H*A]
    attn_kernel<<<dim3(16, 16, 2), 256, attnSmem>>>(qkvP, mask, ctxP);

    // 3) out = ctx @ Wout + bout      [4096,1024] x [1024,1024]
    sgemm128<<<dim3(8, 32), 256>>>(ctxP, Wout, bout, out, 4096, 1024, 1024);
}

// round 2
// speedup vs baseline: 1.1681x; 1.1681x over previous
#include <cuda_runtime.h>

#define NEGV (-1000000000.0f)

// B=2 S=2048 D=1024 H=16 A=64
// qkv row stride = 3*H*A = 3072; M = B*S = 4096

__device__ float g_qkv[(size_t)4096 * 3072];  // 48 MB scratch
__device__ float g_ctx[(size_t)4096 * 1024];  // 16 MB scratch

__device__ __forceinline__ unsigned f2tf32(float x) {
    unsigned y;
    asm("cvt.rna.tf32.f32 %0, %1;" : "=r"(y) : "f"(x));
    return y;
}

__device__ __forceinline__ void mma_tf32(float* d, const unsigned* a, const unsigned* b) {
    asm volatile(
        "mma.sync.aligned.m16n8k8.row.col.f32.tf32.tf32.f32 "
        "{%0,%1,%2,%3}, {%4,%5,%6,%7}, {%8,%9}, {%0,%1,%2,%3};"
        : "+f"(d[0]), "+f"(d[1]), "+f"(d[2]), "+f"(d[3])
        : "r"(a[0]), "r"(a[1]), "r"(a[2]), "r"(a[3]), "r"(b[0]), "r"(b[1]));
}

// ---------------------------------------------------------------------------
// TF32 tensor-core SGEMM: C[M,N] = A[M,K] * B[K,N] (+ bias)
// 128x128 block tile, BK=32, 256 threads (8 warps as 2(M) x 4(N)),
// warp tile 64x32 = 4x4 m16n8k8 mma tiles. Conflict-free padded smem:
//   As pitch 36 -> frag bank = 4g+tig (distinct over 32 lanes)
//   Bs pitch 136 -> frag bank = 8tig+g (distinct over 32 lanes)
// M, N, K must be multiples of 128/128/32 (true for both call sites).
// ---------------------------------------------------------------------------
#define APITCH 36
#define BPITCH 136

__global__ __launch_bounds__(256) void sgemm_tf32(
    const float* __restrict__ A, const float* __restrict__ B,
    const float* __restrict__ bias, float* __restrict__ C,
    int M, int N, int K)
{
    __shared__ unsigned As[128 * APITCH];  // [m][k], k padded 32->36
    __shared__ unsigned Bs[32 * BPITCH];   // [k][n], n padded 128->136

    const int tid = threadIdx.x;
    const int bx = blockIdx.x, by = blockIdx.y;
    const int lane = tid & 31, wid = tid >> 5;
    const int g = lane >> 2, tig = lane & 3;
    const int wm = (wid & 1) * 64;   // warp M offset in block
    const int wn = (wid >> 1) * 32;  // warp N offset in block

    // gmem loader mapping
    const int ra = tid >> 1;              // A row 0..127
    const int ca = (tid & 1) * 16;        // A col half (16 floats)
    const int rb = tid >> 3;              // B row 0..31
    const int cb = (tid & 7) * 16;        // B col chunk (16 floats)

    const float* aptr = A + (size_t)(by * 128 + ra) * K + ca;
    const float* bptr = B + (size_t)rb * N + bx * 128 + cb;

    float acc[4][4][4];
#pragma unroll
    for (int mt = 0; mt < 4; mt++)
#pragma unroll
        for (int nt = 0; nt < 4; nt++)
#pragma unroll
            for (int i = 0; i < 4; i++) acc[mt][nt][i] = 0.0f;

    float4 aR[4], bR[4];
#pragma unroll
    for (int i = 0; i < 4; i++) {
        aR[i] = *(const float4*)(aptr + i * 4);
        bR[i] = *(const float4*)(bptr + i * 4);
    }

    const int nt_iters = K >> 5;
    for (int t = 0;;) {
        // store (cvt to tf32) into smem
#pragma unroll
        for (int i = 0; i < 4; i++) {
            uint4 ua, ub;
            ua.x = f2tf32(aR[i].x); ua.y = f2tf32(aR[i].y);
            ua.z = f2tf32(aR[i].z); ua.w = f2tf32(aR[i].w);
            *(uint4*)&As[ra * APITCH + ca + i * 4] = ua;
            ub.x = f2tf32(bR[i].x); ub.y = f2tf32(bR[i].y);
            ub.z = f2tf32(bR[i].z); ub.w = f2tf32(bR[i].w);
            *(uint4*)&Bs[rb * BPITCH + cb + i * 4] = ub;
        }
        __syncthreads();
        t++;
        if (t < nt_iters) {
#pragma unroll
            for (int i = 0; i < 4; i++) {
                aR[i] = *(const float4*)(aptr + t * 32 + i * 4);
                bR[i] = *(const float4*)(bptr + (size_t)t * 32 * N + i * 4);
            }
        }

#pragma unroll
        for (int ks = 0; ks < 4; ks++) {
            const int k0 = ks * 8;
            unsigned af[4][4], bf[4][2];
#pragma unroll
            for (int mt = 0; mt < 4; mt++) {
                int r0 = wm + mt * 16 + g;
                af[mt][0] = As[r0 * APITCH + k0 + tig];
                af[mt][1] = As[(r0 + 8) * APITCH + k0 + tig];
                af[mt][2] = As[r0 * APITCH + k0 + tig + 4];
                af[mt][3] = As[(r0 + 8) * APITCH + k0 + tig + 4];
            }
#pragma unroll
            for (int nt = 0; nt < 4; nt++) {
                int c0 = wn + nt * 8 + g;
                bf[nt][0] = Bs[(k0 + tig) * BPITCH + c0];
                bf[nt][1] = Bs[(k0 + tig + 4) * BPITCH + c0];
            }
#pragma unroll
            for (int mt = 0; mt < 4; mt++)
#pragma unroll
                for (int nt = 0; nt < 4; nt++)
                    mma_tf32(acc[mt][nt], af[mt], bf[nt]);
        }
        if (t == nt_iters) break;
        __syncthreads();
    }

    // epilogue
    float bv0[4], bv1[4];
#pragma unroll
    for (int nt = 0; nt < 4; nt++) { bv0[nt] = 0.0f; bv1[nt] = 0.0f; }
    if (bias) {
#pragma unroll
        for (int nt = 0; nt < 4; nt++) {
            int col = bx * 128 + wn + nt * 8 + 2 * tig;
            bv0[nt] = bias[col];
            bv1[nt] = bias[col + 1];
        }
    }

#pragma unroll
    for (int mt = 0; mt < 4; mt++) {
        int row = by * 128 + wm + mt * 16 + g;
#pragma unroll
        for (int nt = 0; nt < 4; nt++) {
            int col = bx * 128 + wn + nt * 8 + 2 * tig;
            float2 s0, s1;
            s0.x = acc[mt][nt][0] + bv0[nt];
            s0.y = acc[mt][nt][1] + bv1[nt];
            s1.x = acc[mt][nt][2] + bv0[nt];
            s1.y = acc[mt][nt][3] + bv1[nt];
            *(float2*)(C + (size_t)row * N + col) = s0;
            *(float2*)(C + (size_t)(row + 8) * N + col) = s1;
        }
    }
}

// ---------------------------------------------------------------------------
// Fused attention: per block = one (b, h, 128-row q tile).
// Flash-style online softmax over 32 key tiles of 64. (unchanged, fp32)
// ---------------------------------------------------------------------------
__global__ __launch_bounds__(256) void attn_kernel(
    const float* __restrict__ qkv, const int* __restrict__ mask,
    float* __restrict__ ctx)
{
    extern __shared__ float sm[];
    float* Qs = sm;            // [128][68]
    float* Ks = sm + 8704;     // [64][64]   XOR-swizzled float4 layout
    float* Vs = Ks + 4096;     // [64][64]
    float* Ps = Vs + 4096;     // [128][65]
    float* Mk = Ps + 8320;     // [64]

    const int tid = threadIdx.x;
    const int q0 = blockIdx.x * 128;
    const int h  = blockIdx.y;
    const int b  = blockIdx.z;
    const int rg = tid >> 3;
    const int cg = tid & 7;
    const int r0 = rg * 4;

    const size_t baseRow = (size_t)b * 2048;

#pragma unroll
    for (int i = 0; i < 8; i++) {
        int lin = tid + 256 * i;
        int r = lin >> 4, a4 = lin & 15;
        float4 v = *(const float4*)(qkv + (baseRow + q0 + r) * 3072 + h * 64 + a4 * 4);
        *(float4*)&Qs[r * 68 + a4 * 4] = v;
    }

    float O[4][8];
    float mrow[4], lrow[4];
#pragma unroll
    for (int i = 0; i < 4; i++) {
        mrow[i] = -1e30f;
        lrow[i] = 0.0f;
#pragma unroll
        for (int j = 0; j < 8; j++) O[i][j] = 0.0f;
    }

    for (int t = 0; t < 32; t++) {
        const int k0 = t * 64;
        __syncthreads();

#pragma unroll
        for (int i = 0; i < 4; i++) {
            int lin = tid + 256 * i;
            int k = lin >> 4, a4 = lin & 15;
            const float* src = qkv + (baseRow + k0 + k) * 3072 + h * 64;
            float4 kv = *(const float4*)(src + 1024 + a4 * 4);
            *(float4*)&Ks[(k * 16 + (a4 ^ ((k >> 3) & 7))) * 4] = kv;
            float4 vv = *(const float4*)(src + 2048 + a4 * 4);
            *(float4*)&Vs[k * 64 + a4 * 4] = vv;
        }
        if (tid < 64) Mk[tid] = (float)mask[b * 2048 + k0 + tid];
        __syncthreads();

        float sv[4][8];
#pragma unroll
        for (int i = 0; i < 4; i++)
#pragma unroll
            for (int j = 0; j < 8; j++) sv[i][j] = 0.0f;

#pragma unroll 2
        for (int a4 = 0; a4 < 16; a4++) {
            float4 qf[4];
#pragma unroll
            for (int i = 0; i < 4; i++)
                qf[i] = *(const float4*)&Qs[(r0 + i) * 68 + a4 * 4];
#pragma unroll
            for (int j = 0; j < 8; j++) {
                int c = cg * 8 + j;
                float4 kf = *(const float4*)&Ks[(c * 16 + (a4 ^ ((c >> 3) & 7))) * 4];
#pragma unroll
                for (int i = 0; i < 4; i++)
                    sv[i][j] += qf[i].x * kf.x + qf[i].y * kf.y +
                                qf[i].z * kf.z + qf[i].w * kf.w;
            }
        }

#pragma unroll
        for (int i = 0; i < 4; i++) {
            float mx = -1e30f;
#pragma unroll
            for (int j = 0; j < 8; j++) {
                float x = sv[i][j] * 0.125f;
                x = (Mk[cg * 8 + j] == 0.0f) ? NEGV : x;
                sv[i][j] = x;
                mx = fmaxf(mx, x);
            }
            mx = fmaxf(mx, __shfl_xor_sync(0xffffffffu, mx, 1));
            mx = fmaxf(mx, __shfl_xor_sync(0xffffffffu, mx, 2));
            mx = fmaxf(mx, __shfl_xor_sync(0xffffffffu, mx, 4));
            float mnew = fmaxf(mrow[i], mx);
            float alpha = __expf(mrow[i] - mnew);
            float ps = 0.0f;
#pragma unroll
            for (int j = 0; j < 8; j++) {
                float p = __expf(sv[i][j] - mnew);
                sv[i][j] = p;
                ps += p;
            }
            ps += __shfl_xor_sync(0xffffffffu, ps, 1);
            ps += __shfl_xor_sync(0xffffffffu, ps, 2);
            ps += __shfl_xor_sync(0xffffffffu, ps, 4);
            lrow[i] = lrow[i] * alpha + ps;
            mrow[i] = mnew;
#pragma unroll
            for (int j = 0; j < 8; j++) O[i][j] *= alpha;
#pragma unroll
            for (int j = 0; j < 8; j++)
                Ps[(r0 + i) * 65 + cg * 8 + j] = sv[i][j];
        }
        __syncwarp();

#pragma unroll 4
        for (int k = 0; k < 64; k++) {
            float pv[4];
#pragma unroll
            for (int i = 0; i < 4; i++) pv[i] = Ps[(r0 + i) * 65 + k];
            float vv[8];
            *(float4*)&vv[0] = *(const float4*)&Vs[k * 64 + cg * 8];
            *(float4*)&vv[4] = *(const float4*)&Vs[k * 64 + cg * 8 + 4];
#pragma unroll
            for (int i = 0; i < 4; i++)
#pragma unroll
                for (int j = 0; j < 8; j++)
                    O[i][j] += pv[i] * vv[j];
        }
    }

#pragma unroll
    for (int i = 0; i < 4; i++) {
        float inv = 1.0f / lrow[i];
        float* dst = ctx + (baseRow + q0 + r0 + i) * 1024 + h * 64 + cg * 8;
        float4 o0, o1;
        o0.x = O[i][0] * inv; o0.y = O[i][1] * inv;
        o0.z = O[i][2] * inv; o0.w = O[i][3] * inv;
        o1.x = O[i][4] * inv; o1.y = O[i][5] * inv;
        o1.z = O[i][6] * inv; o1.w = O[i][7] * inv;
        *(float4*)&dst[0] = o0;
        *(float4*)&dst[4] = o1;
    }
}

// ---------------------------------------------------------------------------
extern "C" void kernel_launch(void* const* d_in, const int* in_sizes, int n_in,
                              void* d_out, int out_size)
{
    const float* qs   = (const float*)d_in[0];
    const int*   mask = (const int*)d_in[1];
    const float* Wqkv = (const float*)d_in[2];
    const float* Wout = (const float*)d_in[3];
    const float* bout = (const float*)d_in[4];
    float* out = (float*)d_out;

    float *qkvP, *ctxP;
    cudaGetSymbolAddress((void**)&qkvP, g_qkv);
    cudaGetSymbolAddress((void**)&ctxP, g_ctx);

    const int attnSmem = 25280 * 4;  // 101120 bytes
    cudaFuncSetAttribute(attn_kernel,
                         cudaFuncAttributeMaxDynamicSharedMemorySize, attnSmem);

    // 1) qkv = qs @ Wqkv              [4096,1024] x [1024,3072]
    sgemm_tf32<<<dim3(24, 32), 256>>>(qs, Wqkv, nullptr, qkvP, 4096, 3072, 1024);

    // 2) fused masked attention -> ctx [B,S,H*A]
    attn_kernel<<<dim3(16, 16, 2), 256, attnSmem>>>(qkvP, mask, ctxP);

    // 3) out = ctx @ Wout + bout      [4096,1024] x [1024,1024]
    sgemm_tf32<<<dim3(8, 32), 256>>>(ctxP, Wout, bout, out, 4096, 1024, 1024);
}

// round 3
// speedup vs baseline: 2.2474x; 1.9240x over previous
#include <cuda_runtime.h>

#define NEGV (-1000000000.0f)

// B=2 S=2048 D=1024 H=16 A=64
// qkv row stride = 3*H*A = 3072; M = B*S = 4096

__device__ float g_qkv[(size_t)4096 * 3072];  // 48 MB scratch
__device__ float g_ctx[(size_t)4096 * 1024];  // 16 MB scratch

__device__ __forceinline__ unsigned f2tf32(float x) {
    unsigned y;
    asm("cvt.rna.tf32.f32 %0, %1;" : "=r"(y) : "f"(x));
    return y;
}

__device__ __forceinline__ void mma_tf32(float* d, const unsigned* a, const unsigned* b) {
    asm volatile(
        "mma.sync.aligned.m16n8k8.row.col.f32.tf32.tf32.f32 "
        "{%0,%1,%2,%3}, {%4,%5,%6,%7}, {%8,%9}, {%0,%1,%2,%3};"
        : "+f"(d[0]), "+f"(d[1]), "+f"(d[2]), "+f"(d[3])
        : "r"(a[0]), "r"(a[1]), "r"(a[2]), "r"(a[3]), "r"(b[0]), "r"(b[1]));
}

// ---------------------------------------------------------------------------
// TF32 tensor-core SGEMM (unchanged from round 2 — proven)
// ---------------------------------------------------------------------------
#define APITCH 36
#define BPITCH 136

__global__ __launch_bounds__(256) void sgemm_tf32(
    const float* __restrict__ A, const float* __restrict__ B,
    const float* __restrict__ bias, float* __restrict__ C,
    int M, int N, int K)
{
    __shared__ unsigned As[128 * APITCH];
    __shared__ unsigned Bs[32 * BPITCH];

    const int tid = threadIdx.x;
    const int bx = blockIdx.x, by = blockIdx.y;
    const int lane = tid & 31, wid = tid >> 5;
    const int g = lane >> 2, tig = lane & 3;
    const int wm = (wid & 1) * 64;
    const int wn = (wid >> 1) * 32;

    const int ra = tid >> 1;
    const int ca = (tid & 1) * 16;
    const int rb = tid >> 3;
    const int cb = (tid & 7) * 16;

    const float* aptr = A + (size_t)(by * 128 + ra) * K + ca;
    const float* bptr = B + (size_t)rb * N + bx * 128 + cb;

    float acc[4][4][4];
#pragma unroll
    for (int mt = 0; mt < 4; mt++)
#pragma unroll
        for (int nt = 0; nt < 4; nt++)
#pragma unroll
            for (int i = 0; i < 4; i++) acc[mt][nt][i] = 0.0f;

    float4 aR[4], bR[4];
#pragma unroll
    for (int i = 0; i < 4; i++) {
        aR[i] = *(const float4*)(aptr + i * 4);
        bR[i] = *(const float4*)(bptr + i * 4);
    }

    const int nt_iters = K >> 5;
    for (int t = 0;;) {
#pragma unroll
        for (int i = 0; i < 4; i++) {
            uint4 ua, ub;
            ua.x = f2tf32(aR[i].x); ua.y = f2tf32(aR[i].y);
            ua.z = f2tf32(aR[i].z); ua.w = f2tf32(aR[i].w);
            *(uint4*)&As[ra * APITCH + ca + i * 4] = ua;
            ub.x = f2tf32(bR[i].x); ub.y = f2tf32(bR[i].y);
            ub.z = f2tf32(bR[i].z); ub.w = f2tf32(bR[i].w);
            *(uint4*)&Bs[rb * BPITCH + cb + i * 4] = ub;
        }
        __syncthreads();
        t++;
        if (t < nt_iters) {
#pragma unroll
            for (int i = 0; i < 4; i++) {
                aR[i] = *(const float4*)(aptr + t * 32 + i * 4);
                bR[i] = *(const float4*)(bptr + (size_t)t * 32 * N + i * 4);
            }
        }

#pragma unroll
        for (int ks = 0; ks < 4; ks++) {
            const int k0 = ks * 8;
            unsigned af[4][4], bf[4][2];
#pragma unroll
            for (int mt = 0; mt < 4; mt++) {
                int r0 = wm + mt * 16 + g;
                af[mt][0] = As[r0 * APITCH + k0 + tig];
                af[mt][1] = As[(r0 + 8) * APITCH + k0 + tig];
                af[mt][2] = As[r0 * APITCH + k0 + tig + 4];
                af[mt][3] = As[(r0 + 8) * APITCH + k0 + tig + 4];
            }
#pragma unroll
            for (int nt = 0; nt < 4; nt++) {
                int c0 = wn + nt * 8 + g;
                bf[nt][0] = Bs[(k0 + tig) * BPITCH + c0];
                bf[nt][1] = Bs[(k0 + tig + 4) * BPITCH + c0];
            }
#pragma unroll
            for (int mt = 0; mt < 4; mt++)
#pragma unroll
                for (int nt = 0; nt < 4; nt++)
                    mma_tf32(acc[mt][nt], af[mt], bf[nt]);
        }
        if (t == nt_iters) break;
        __syncthreads();
    }

    float bv0[4], bv1[4];
#pragma unroll
    for (int nt = 0; nt < 4; nt++) { bv0[nt] = 0.0f; bv1[nt] = 0.0f; }
    if (bias) {
#pragma unroll
        for (int nt = 0; nt < 4; nt++) {
            int col = bx * 128 + wn + nt * 8 + 2 * tig;
            bv0[nt] = bias[col];
            bv1[nt] = bias[col + 1];
        }
    }

#pragma unroll
    for (int mt = 0; mt < 4; mt++) {
        int row = by * 128 + wm + mt * 16 + g;
#pragma unroll
        for (int nt = 0; nt < 4; nt++) {
            int col = bx * 128 + wn + nt * 8 + 2 * tig;
            float2 s0, s1;
            s0.x = acc[mt][nt][0] + bv0[nt];
            s0.y = acc[mt][nt][1] + bv1[nt];
            s1.x = acc[mt][nt][2] + bv0[nt];
            s1.y = acc[mt][nt][3] + bv1[nt];
            *(float2*)(C + (size_t)row * N + col) = s0;
            *(float2*)(C + (size_t)(row + 8) * N + col) = s1;
        }
    }
}

// ---------------------------------------------------------------------------
// Tensor-core flash attention.
// Block = (128-row q tile, h, b); 256 threads = 8 warps; warp w -> 16 rows.
// mma.m16n8k8.tf32:
//   Q: A-operand, fragments hoisted to registers (Qf smem pitch 68, bank=g*4+tig+c)
//   K: B-operand read as Kf[key*68 + dim]   (natural layout!  bank=g*4+tig+c)
//   V: B-operand read as Vf[key*72 + dim]   (natural layout!  bank=tig*8+g+c)
//   P: round-trip via smem aliasing Qf (warp-local rows -> __syncwarp only)
// Softmax on C-fragment layout; row stats across the 4 tig-lanes via shfl.
// ---------------------------------------------------------------------------
#define QP 68
#define VP 72

__global__ __launch_bounds__(256, 1) void attn_tc(
    const float* __restrict__ qkv, const int* __restrict__ mask,
    float* __restrict__ ctx)
{
    extern __shared__ unsigned sm[];
    unsigned* Qf = sm;                       // [128][68]  (aliased by Ps)
    unsigned* Kf = sm + 128 * QP;            // [64 keys][68 dims]
    unsigned* Vf = Kf + 64 * QP;             // [64 keys][72 dims]
    float*    Mk = (float*)(Vf + 64 * VP);   // [64]
    unsigned* Ps = Qf;                       // alias: Q consumed before first P write

    const int tid = threadIdx.x;
    const int lane = tid & 31, wid = tid >> 5;
    const int g = lane >> 2, tig = lane & 3;
    const int W = wid * 16;                  // warp's row offset in q tile

    const int q0 = blockIdx.x * 128;
    const int h  = blockIdx.y;
    const int b  = blockIdx.z;
    const size_t baseRow = (size_t)b * 2048;

    // ---- prologue: Q tile -> smem (tf32, A-layout), then to registers ----
#pragma unroll
    for (int i = 0; i < 8; i++) {
        int lin = tid + 256 * i;
        int r = lin >> 4, a4 = lin & 15;
        float4 v = *(const float4*)(qkv + (baseRow + q0 + r) * 3072 + h * 64 + a4 * 4);
        uint4 u;
        u.x = f2tf32(v.x); u.y = f2tf32(v.y); u.z = f2tf32(v.z); u.w = f2tf32(v.w);
        *(uint4*)&Qf[r * QP + a4 * 4] = u;
    }
    __syncthreads();

    unsigned qa[8][4];
#pragma unroll
    for (int ks = 0; ks < 8; ks++) {
        qa[ks][0] = Qf[(W + g) * QP + ks * 8 + tig];
        qa[ks][1] = Qf[(W + g + 8) * QP + ks * 8 + tig];
        qa[ks][2] = Qf[(W + g) * QP + ks * 8 + tig + 4];
        qa[ks][3] = Qf[(W + g + 8) * QP + ks * 8 + tig + 4];
    }
    __syncthreads();  // Q fully consumed; Ps may now overwrite Qf

    float O[8][4];
#pragma unroll
    for (int nt = 0; nt < 8; nt++)
#pragma unroll
        for (int i = 0; i < 4; i++) O[nt][i] = 0.0f;
    float mA = -1e30f, mB = -1e30f, lA = 0.0f, lB = 0.0f;

    for (int t = 0; t < 32; t++) {
        const int k0g = t * 64;
        __syncthreads();  // all warps done reading Kf/Vf from previous tile

        // ---- load K, V tiles (natural layout, tf32) + mask ----
#pragma unroll
        for (int i = 0; i < 4; i++) {
            int lin = tid + 256 * i;
            int key = lin >> 4, a4 = lin & 15;
            const float* src = qkv + (baseRow + k0g + key) * 3072 + h * 64;
            float4 kv = *(const float4*)(src + 1024 + a4 * 4);
            uint4 uk;
            uk.x = f2tf32(kv.x); uk.y = f2tf32(kv.y);
            uk.z = f2tf32(kv.z); uk.w = f2tf32(kv.w);
            *(uint4*)&Kf[key * QP + a4 * 4] = uk;
            float4 vv = *(const float4*)(src + 2048 + a4 * 4);
            uint4 uv;
            uv.x = f2tf32(vv.x); uv.y = f2tf32(vv.y);
            uv.z = f2tf32(vv.z); uv.w = f2tf32(vv.w);
            *(uint4*)&Vf[key * VP + a4 * 4] = uv;
        }
        if (tid < 64) Mk[tid] = (float)mask[b * 2048 + k0g + tid];
        __syncthreads();

        // ---- S = Q K^T via mma ----
        float s[8][4];
#pragma unroll
        for (int nt = 0; nt < 8; nt++)
#pragma unroll
            for (int i = 0; i < 4; i++) s[nt][i] = 0.0f;

#pragma unroll
        for (int nt = 0; nt < 8; nt++) {
            const int key = nt * 8 + g;
#pragma unroll
            for (int ks = 0; ks < 8; ks++) {
                unsigned bf[2];
                bf[0] = Kf[key * QP + ks * 8 + tig];
                bf[1] = Kf[key * QP + ks * 8 + tig + 4];
                mma_tf32(s[nt], qa[ks], bf);
            }
        }

        // ---- mask + online softmax on fragment layout ----
        float mxA = -1e30f, mxB = -1e30f;
#pragma unroll
        for (int nt = 0; nt < 8; nt++) {
            const int c = nt * 8 + 2 * tig;
            const float m0 = Mk[c], m1 = Mk[c + 1];
            s[nt][0] = (m0 == 0.0f) ? NEGV : s[nt][0] * 0.125f;
            s[nt][1] = (m1 == 0.0f) ? NEGV : s[nt][1] * 0.125f;
            s[nt][2] = (m0 == 0.0f) ? NEGV : s[nt][2] * 0.125f;
            s[nt][3] = (m1 == 0.0f) ? NEGV : s[nt][3] * 0.125f;
            mxA = fmaxf(mxA, fmaxf(s[nt][0], s[nt][1]));
            mxB = fmaxf(mxB, fmaxf(s[nt][2], s[nt][3]));
        }
        mxA = fmaxf(mxA, __shfl_xor_sync(0xffffffffu, mxA, 1));
        mxA = fmaxf(mxA, __shfl_xor_sync(0xffffffffu, mxA, 2));
        mxB = fmaxf(mxB, __shfl_xor_sync(0xffffffffu, mxB, 1));
        mxB = fmaxf(mxB, __shfl_xor_sync(0xffffffffu, mxB, 2));

        const float mnA = fmaxf(mA, mxA);
        const float mnB = fmaxf(mB, mxB);
        const float alphaA = __expf(mA - mnA);
        const float alphaB = __expf(mB - mnB);
        float sumA = 0.0f, sumB = 0.0f;
#pragma unroll
        for (int nt = 0; nt < 8; nt++) {
            s[nt][0] = __expf(s[nt][0] - mnA);
            s[nt][1] = __expf(s[nt][1] - mnA);
            s[nt][2] = __expf(s[nt][2] - mnB);
            s[nt][3] = __expf(s[nt][3] - mnB);
            sumA += s[nt][0] + s[nt][1];
            sumB += s[nt][2] + s[nt][3];
        }
        sumA += __shfl_xor_sync(0xffffffffu, sumA, 1);
        sumA += __shfl_xor_sync(0xffffffffu, sumA, 2);
        sumB += __shfl_xor_sync(0xffffffffu, sumB, 1);
        sumB += __shfl_xor_sync(0xffffffffu, sumB, 2);
        lA = lA * alphaA + sumA;  mA = mnA;
        lB = lB * alphaB + sumB;  mB = mnB;
#pragma unroll
        for (int nt = 0; nt < 8; nt++) {
            O[nt][0] *= alphaA; O[nt][1] *= alphaA;
            O[nt][2] *= alphaB; O[nt][3] *= alphaB;
        }

        // ---- P -> smem (tf32, A-layout); rows are warp-local ----
#pragma unroll
        for (int nt = 0; nt < 8; nt++) {
            const int c = nt * 8 + 2 * tig;
            Ps[(W + g) * QP + c]     = f2tf32(s[nt][0]);
            Ps[(W + g) * QP + c + 1] = f2tf32(s[nt][1]);
            Ps[(W + g + 8) * QP + c]     = f2tf32(s[nt][2]);
            Ps[(W + g + 8) * QP + c + 1] = f2tf32(s[nt][3]);
        }
        __syncwarp();

        unsigned pa[8][4];
#pragma unroll
        for (int ks = 0; ks < 8; ks++) {
            pa[ks][0] = Ps[(W + g) * QP + ks * 8 + tig];
            pa[ks][1] = Ps[(W + g + 8) * QP + ks * 8 + tig];
            pa[ks][2] = Ps[(W + g) * QP + ks * 8 + tig + 4];
            pa[ks][3] = Ps[(W + g + 8) * QP + ks * 8 + tig + 4];
        }

        // ---- O += P V via mma ----
#pragma unroll
        for (int nt = 0; nt < 8; nt++) {
            const int d = nt * 8 + g;
#pragma unroll
            for (int ks = 0; ks < 8; ks++) {
                unsigned bf[2];
                bf[0] = Vf[(ks * 8 + tig) * VP + d];
                bf[1] = Vf[(ks * 8 + tig + 4) * VP + d];
                mma_tf32(O[nt], pa[ks], bf);
            }
        }
    }

    // ---- epilogue ----
    const float invA = 1.0f / lA;
    const float invB = 1.0f / lB;
    const size_t rowA = baseRow + q0 + W + g;
#pragma unroll
    for (int nt = 0; nt < 8; nt++) {
        const int col = h * 64 + nt * 8 + 2 * tig;
        float2 oA, oB;
        oA.x = O[nt][0] * invA; oA.y = O[nt][1] * invA;
        oB.x = O[nt][2] * invB; oB.y = O[nt][3] * invB;
        *(float2*)(ctx + rowA * 1024 + col) = oA;
        *(float2*)(ctx + (rowA + 8) * 1024 + col) = oB;
    }
}

// ---------------------------------------------------------------------------
extern "C" void kernel_launch(void* const* d_in, const int* in_sizes, int n_in,
                              void* d_out, int out_size)
{
    const float* qs   = (const float*)d_in[0];
    const int*   mask = (const int*)d_in[1];
    const float* Wqkv = (const float*)d_in[2];
    const float* Wout = (const float*)d_in[3];
    const float* bout = (const float*)d_in[4];
    float* out = (float*)d_out;

    float *qkvP, *ctxP;
    cudaGetSymbolAddress((void**)&qkvP, g_qkv);
    cudaGetSymbolAddress((void**)&ctxP, g_ctx);

    // smem: Qf 128*68 + Kf 64*68 + Vf 64*72 + Mk 64  (words)
    const int attnSmem = (128 * QP + 64 * QP + 64 * VP + 64) * 4;  // 70912 B
    cudaFuncSetAttribute(attn_tc,
                         cudaFuncAttributeMaxDynamicSharedMemorySize, attnSmem);

    // 1) qkv = qs @ Wqkv              [4096,1024] x [1024,3072]
    sgemm_tf32<<<dim3(24, 32), 256>>>(qs, Wqkv, nullptr, qkvP, 4096, 3072, 1024);

    // 2) fused masked attention -> ctx [B,S,H*A]
    attn_tc<<<dim3(16, 16, 2), 256, attnSmem>>>(qkvP, mask, ctxP);

    // 3) out = ctx @ Wout + bout      [4096,1024] x [1024,1024]
    sgemm_tf32<<<dim3(8, 32), 256>>>(ctxP, Wout, bout, out, 4096, 1024, 1024);
}

// round 4
// speedup vs baseline: 2.4677x; 1.0980x over previous
#include <cuda_runtime.h>

#define NEGV (-1000000000.0f)

// B=2 S=2048 D=1024 H=16 A=64
// qkv row stride = 3*H*A = 3072; M = B*S = 4096

__device__ float g_qkv[(size_t)4096 * 3072];  // 48 MB scratch
__device__ float g_ctx[(size_t)4096 * 1024];  // 16 MB scratch

__device__ __forceinline__ unsigned f2tf32(float x) {
    unsigned y;
    asm("cvt.rna.tf32.f32 %0, %1;" : "=r"(y) : "f"(x));
    return y;
}

__device__ __forceinline__ void mma_tf32(float* d, const unsigned* a, const unsigned* b) {
    asm volatile(
        "mma.sync.aligned.m16n8k8.row.col.f32.tf32.tf32.f32 "
        "{%0,%1,%2,%3}, {%4,%5,%6,%7}, {%8,%9}, {%0,%1,%2,%3};"
        : "+f"(d[0]), "+f"(d[1]), "+f"(d[2]), "+f"(d[3])
        : "r"(a[0]), "r"(a[1]), "r"(a[2]), "r"(a[3]), "r"(b[0]), "r"(b[1]));
}

__device__ __forceinline__ unsigned sptr(const void* p) {
    return (unsigned)__cvta_generic_to_shared(p);
}

__device__ __forceinline__ void cpa16(unsigned s, const void* g) {
    asm volatile("cp.async.cg.shared.global [%0], [%1], 16;\n" :: "r"(s), "l"(g));
}

// ---------------------------------------------------------------------------
// TF32 tensor-core SGEMM: C = A*B (+bias)
// 128x128 tile, BK=32, 256 threads (8 warps 2x4), warp tile 64x32.
// Round 4: cp.async + 2-stage double buffer, 2 CTAs/SM (regs<=128),
// tf32 cvt moved to fragment-load time (round-to-nearest, unbiased).
// Padded smem (APITCH 36 / BPITCH 136) keeps fragment LDS conflict-free.
// ---------------------------------------------------------------------------
#define APITCH 36
#define BPITCH 136
#define ASTAGE (128 * APITCH)
#define BSTAGE (32 * BPITCH)

__global__ __launch_bounds__(256, 2) void sgemm_tf32(
    const float* __restrict__ A, const float* __restrict__ B,
    const float* __restrict__ bias, float* __restrict__ C,
    int M, int N, int K)
{
    extern __shared__ float smg[];
    float* As = smg;                 // [2][128*36]
    float* Bs = smg + 2 * ASTAGE;    // [2][32*136]

    const int tid = threadIdx.x;
    const int bx = blockIdx.x, by = blockIdx.y;
    const int lane = tid & 31, wid = tid >> 5;
    const int g = lane >> 2, tig = lane & 3;
    const int wm = (wid & 1) * 64;
    const int wn = (wid >> 1) * 32;

    // gmem loader mapping
    const int ra = tid >> 1;              // A row 0..127
    const int ca = (tid & 1) * 16;        // A col half
    const int rb = tid >> 3;              // B row 0..31
    const int cb = (tid & 7) * 16;        // B col chunk

    const float* aptr = A + (size_t)(by * 128 + ra) * K + ca;
    const float* bptr = B + (size_t)rb * N + bx * 128 + cb;

    const unsigned sa_base = sptr(&As[ra * APITCH + ca]);
    const unsigned sb_base = sptr(&Bs[rb * BPITCH + cb]);

    float acc[4][4][4];
#pragma unroll
    for (int mt = 0; mt < 4; mt++)
#pragma unroll
        for (int nt = 0; nt < 4; nt++)
#pragma unroll
            for (int i = 0; i < 4; i++) acc[mt][nt][i] = 0.0f;

    const int nt_iters = K >> 5;

    // issue stage 0
    {
        const float* ag = aptr;
        const float* bg = bptr;
#pragma unroll
        for (int i = 0; i < 4; i++) cpa16(sa_base + i * 16, ag + i * 4);
#pragma unroll
        for (int i = 0; i < 4; i++) cpa16(sb_base + i * 16, bg + i * 4);
        asm volatile("cp.async.commit_group;\n");
    }

    for (int t = 0; t < nt_iters; t++) {
        if (t + 1 < nt_iters) {
            const int s = (t + 1) & 1;
            const float* ag = aptr + (t + 1) * 32;
            const float* bg = bptr + (size_t)(t + 1) * 32 * N;
            const unsigned sa = sa_base + s * (ASTAGE * 4);
            const unsigned sb = sb_base + s * (BSTAGE * 4) + (2 * ASTAGE - ASTAGE) * 0;
#pragma unroll
            for (int i = 0; i < 4; i++) cpa16(sa + i * 16, ag + i * 4);
#pragma unroll
            for (int i = 0; i < 4; i++) cpa16(sb + i * 16, bg + i * 4);
            asm volatile("cp.async.commit_group;\n");
            asm volatile("cp.async.wait_group 1;\n");
        } else {
            asm volatile("cp.async.wait_group 0;\n");
        }
        __syncthreads();

        const float* Ab = As + (t & 1) * ASTAGE;
        const float* Bb = Bs + (t & 1) * BSTAGE;

#pragma unroll
        for (int ks = 0; ks < 4; ks++) {
            const int k0 = ks * 8;
            unsigned af[4][4], bf[4][2];
#pragma unroll
            for (int mt = 0; mt < 4; mt++) {
                int r0 = wm + mt * 16 + g;
                af[mt][0] = f2tf32(Ab[r0 * APITCH + k0 + tig]);
                af[mt][1] = f2tf32(Ab[(r0 + 8) * APITCH + k0 + tig]);
                af[mt][2] = f2tf32(Ab[r0 * APITCH + k0 + tig + 4]);
                af[mt][3] = f2tf32(Ab[(r0 + 8) * APITCH + k0 + tig + 4]);
            }
#pragma unroll
            for (int nt = 0; nt < 4; nt++) {
                int c0 = wn + nt * 8 + g;
                bf[nt][0] = f2tf32(Bb[(k0 + tig) * BPITCH + c0]);
                bf[nt][1] = f2tf32(Bb[(k0 + tig + 4) * BPITCH + c0]);
            }
#pragma unroll
            for (int mt = 0; mt < 4; mt++)
#pragma unroll
                for (int nt = 0; nt < 4; nt++)
                    mma_tf32(acc[mt][nt], af[mt], bf[nt]);
        }
        __syncthreads();
    }

    // epilogue
    float bv0[4], bv1[4];
#pragma unroll
    for (int nt = 0; nt < 4; nt++) { bv0[nt] = 0.0f; bv1[nt] = 0.0f; }
    if (bias) {
#pragma unroll
        for (int nt = 0; nt < 4; nt++) {
            int col = bx * 128 + wn + nt * 8 + 2 * tig;
            bv0[nt] = bias[col];
            bv1[nt] = bias[col + 1];
        }
    }

#pragma unroll
    for (int mt = 0; mt < 4; mt++) {
        int row = by * 128 + wm + mt * 16 + g;
#pragma unroll
        for (int nt = 0; nt < 4; nt++) {
            int col = bx * 128 + wn + nt * 8 + 2 * tig;
            float2 s0, s1;
            s0.x = acc[mt][nt][0] + bv0[nt];
            s0.y = acc[mt][nt][1] + bv1[nt];
            s1.x = acc[mt][nt][2] + bv0[nt];
            s1.y = acc[mt][nt][3] + bv1[nt];
            *(float2*)(C + (size_t)row * N + col) = s0;
            *(float2*)(C + (size_t)(row + 8) * N + col) = s1;
        }
    }
}

// ---------------------------------------------------------------------------
// Tensor-core flash attention (unchanged from round 3 — proven).
// ---------------------------------------------------------------------------
#define QP 68
#define VP 72

__global__ __launch_bounds__(256, 1) void attn_tc(
    const float* __restrict__ qkv, const int* __restrict__ mask,
    float* __restrict__ ctx)
{
    extern __shared__ unsigned sm[];
    unsigned* Qf = sm;                       // [128][68]  (aliased by Ps)
    unsigned* Kf = sm + 128 * QP;            // [64 keys][68 dims]
    unsigned* Vf = Kf + 64 * QP;             // [64 keys][72 dims]
    float*    Mk = (float*)(Vf + 64 * VP);   // [64]
    unsigned* Ps = Qf;

    const int tid = threadIdx.x;
    const int lane = tid & 31, wid = tid >> 5;
    const int g = lane >> 2, tig = lane & 3;
    const int W = wid * 16;

    const int q0 = blockIdx.x * 128;
    const int h  = blockIdx.y;
    const int b  = blockIdx.z;
    const size_t baseRow = (size_t)b * 2048;

#pragma unroll
    for (int i = 0; i < 8; i++) {
        int lin = tid + 256 * i;
        int r = lin >> 4, a4 = lin & 15;
        float4 v = *(const float4*)(qkv + (baseRow + q0 + r) * 3072 + h * 64 + a4 * 4);
        uint4 u;
        u.x = f2tf32(v.x); u.y = f2tf32(v.y); u.z = f2tf32(v.z); u.w = f2tf32(v.w);
        *(uint4*)&Qf[r * QP + a4 * 4] = u;
    }
    __syncthreads();

    unsigned qa[8][4];
#pragma unroll
    for (int ks = 0; ks < 8; ks++) {
        qa[ks][0] = Qf[(W + g) * QP + ks * 8 + tig];
        qa[ks][1] = Qf[(W + g + 8) * QP + ks * 8 + tig];
        qa[ks][2] = Qf[(W + g) * QP + ks * 8 + tig + 4];
        qa[ks][3] = Qf[(W + g + 8) * QP + ks * 8 + tig + 4];
    }
    __syncthreads();

    float O[8][4];
#pragma unroll
    for (int nt = 0; nt < 8; nt++)
#pragma unroll
        for (int i = 0; i < 4; i++) O[nt][i] = 0.0f;
    float mA = -1e30f, mB = -1e30f, lA = 0.0f, lB = 0.0f;

    for (int t = 0; t < 32; t++) {
        const int k0g = t * 64;
        __syncthreads();

#pragma unroll
        for (int i = 0; i < 4; i++) {
            int lin = tid + 256 * i;
            int key = lin >> 4, a4 = lin & 15;
            const float* src = qkv + (baseRow + k0g + key) * 3072 + h * 64;
            float4 kv = *(const float4*)(src + 1024 + a4 * 4);
            uint4 uk;
            uk.x = f2tf32(kv.x); uk.y = f2tf32(kv.y);
            uk.z = f2tf32(kv.z); uk.w = f2tf32(kv.w);
            *(uint4*)&Kf[key * QP + a4 * 4] = uk;
            float4 vv = *(const float4*)(src + 2048 + a4 * 4);
            uint4 uv;
            uv.x = f2tf32(vv.x); uv.y = f2tf32(vv.y);
            uv.z = f2tf32(vv.z); uv.w = f2tf32(vv.w);
            *(uint4*)&Vf[key * VP + a4 * 4] = uv;
        }
        if (tid < 64) Mk[tid] = (float)mask[b * 2048 + k0g + tid];
        __syncthreads();

        float s[8][4];
#pragma unroll
        for (int nt = 0; nt < 8; nt++)
#pragma unroll
            for (int i = 0; i < 4; i++) s[nt][i] = 0.0f;

#pragma unroll
        for (int nt = 0; nt < 8; nt++) {
            const int key = nt * 8 + g;
#pragma unroll
            for (int ks = 0; ks < 8; ks++) {
                unsigned bf[2];
                bf[0] = Kf[key * QP + ks * 8 + tig];
                bf[1] = Kf[key * QP + ks * 8 + tig + 4];
                mma_tf32(s[nt], qa[ks], bf);
            }
        }

        float mxA = -1e30f, mxB = -1e30f;
#pragma unroll
        for (int nt = 0; nt < 8; nt++) {
            const int c = nt * 8 + 2 * tig;
            const float m0 = Mk[c], m1 = Mk[c + 1];
            s[nt][0] = (m0 == 0.0f) ? NEGV : s[nt][0] * 0.125f;
            s[nt][1] = (m1 == 0.0f) ? NEGV : s[nt][1] * 0.125f;
            s[nt][2] = (m0 == 0.0f) ? NEGV : s[nt][2] * 0.125f;
            s[nt][3] = (m1 == 0.0f) ? NEGV : s[nt][3] * 0.125f;
            mxA = fmaxf(mxA, fmaxf(s[nt][0], s[nt][1]));
            mxB = fmaxf(mxB, fmaxf(s[nt][2], s[nt][3]));
        }
        mxA = fmaxf(mxA, __shfl_xor_sync(0xffffffffu, mxA, 1));
        mxA = fmaxf(mxA, __shfl_xor_sync(0xffffffffu, mxA, 2));
        mxB = fmaxf(mxB, __shfl_xor_sync(0xffffffffu, mxB, 1));
        mxB = fmaxf(mxB, __shfl_xor_sync(0xffffffffu, mxB, 2));

        const float mnA = fmaxf(mA, mxA);
        const float mnB = fmaxf(mB, mxB);
        const float alphaA = __expf(mA - mnA);
        const float alphaB = __expf(mB - mnB);
        float sumA = 0.0f, sumB = 0.0f;
#pragma unroll
        for (int nt = 0; nt < 8; nt++) {
            s[nt][0] = __expf(s[nt][0] - mnA);
            s[nt][1] = __expf(s[nt][1] - mnA);
            s[nt][2] = __expf(s[nt][2] - mnB);
            s[nt][3] = __expf(s[nt][3] - mnB);
            sumA += s[nt][0] + s[nt][1];
            sumB += s[nt][2] + s[nt][3];
        }
        sumA += __shfl_xor_sync(0xffffffffu, sumA, 1);
        sumA += __shfl_xor_sync(0xffffffffu, sumA, 2);
        sumB += __shfl_xor_sync(0xffffffffu, sumB, 1);
        sumB += __shfl_xor_sync(0xffffffffu, sumB, 2);
        lA = lA * alphaA + sumA;  mA = mnA;
        lB = lB * alphaB + sumB;  mB = mnB;
#pragma unroll
        for (int nt = 0; nt < 8; nt++) {
            O[nt][0] *= alphaA; O[nt][1] *= alphaA;
            O[nt][2] *= alphaB; O[nt][3] *= alphaB;
        }

#pragma unroll
        for (int nt = 0; nt < 8; nt++) {
            const int c = nt * 8 + 2 * tig;
            Ps[(W + g) * QP + c]     = f2tf32(s[nt][0]);
            Ps[(W + g) * QP + c + 1] = f2tf32(s[nt][1]);
            Ps[(W + g + 8) * QP + c]     = f2tf32(s[nt][2]);
            Ps[(W + g + 8) * QP + c + 1] = f2tf32(s[nt][3]);
        }
        __syncwarp();

        unsigned pa[8][4];
#pragma unroll
        for (int ks = 0; ks < 8; ks++) {
            pa[ks][0] = Ps[(W + g) * QP + ks * 8 + tig];
            pa[ks][1] = Ps[(W + g + 8) * QP + ks * 8 + tig];
            pa[ks][2] = Ps[(W + g) * QP + ks * 8 + tig + 4];
            pa[ks][3] = Ps[(W + g + 8) * QP + ks * 8 + tig + 4];
        }

#pragma unroll
        for (int nt = 0; nt < 8; nt++) {
            const int d = nt * 8 + g;
#pragma unroll
            for (int ks = 0; ks < 8; ks++) {
                unsigned bf[2];
                bf[0] = Vf[(ks * 8 + tig) * VP + d];
                bf[1] = Vf[(ks * 8 + tig + 4) * VP + d];
                mma_tf32(O[nt], pa[ks], bf);
            }
        }
    }

    const float invA = 1.0f / lA;
    const float invB = 1.0f / lB;
    const size_t rowA = baseRow + q0 + W + g;
#pragma unroll
    for (int nt = 0; nt < 8; nt++) {
        const int col = h * 64 + nt * 8 + 2 * tig;
        float2 oA, oB;
        oA.x = O[nt][0] * invA; oA.y = O[nt][1] * invA;
        oB.x = O[nt][2] * invB; oB.y = O[nt][3] * invB;
        *(float2*)(ctx + rowA * 1024 + col) = oA;
        *(float2*)(ctx + (rowA + 8) * 1024 + col) = oB;
    }
}

// ---------------------------------------------------------------------------
extern "C" void kernel_launch(void* const* d_in, const int* in_sizes, int n_in,
                              void* d_out, int out_size)
{
    const float* qs   = (const float*)d_in[0];
    const int*   mask = (const int*)d_in[1];
    const float* Wqkv = (const float*)d_in[2];
    const float* Wout = (const float*)d_in[3];
    const float* bout = (const float*)d_in[4];
    float* out = (float*)d_out;

    float *qkvP, *ctxP;
    cudaGetSymbolAddress((void**)&qkvP, g_qkv);
    cudaGetSymbolAddress((void**)&ctxP, g_ctx);

    const int gemmSmem = 2 * (ASTAGE + BSTAGE) * 4;  // 71680 B
    cudaFuncSetAttribute(sgemm_tf32,
                         cudaFuncAttributeMaxDynamicSharedMemorySize, gemmSmem);

    const int attnSmem = (128 * QP + 64 * QP + 64 * VP + 64) * 4;  // 70912 B
    cudaFuncSetAttribute(attn_tc,
                         cudaFuncAttributeMaxDynamicSharedMemorySize, attnSmem);

    // 1) qkv = qs @ Wqkv              [4096,1024] x [1024,3072]
    sgemm_tf32<<<dim3(24, 32), 256, gemmSmem>>>(qs, Wqkv, nullptr, qkvP, 4096, 3072, 1024);

    // 2) fused masked attention -> ctx [B,S,H*A]
    attn_tc<<<dim3(16, 16, 2), 256, attnSmem>>>(qkvP, mask, ctxP);

    // 3) out = ctx @ Wout + bout      [4096,1024] x [1024,1024]
    sgemm_tf32<<<dim3(8, 32), 256, gemmSmem>>>(ctxP, Wout, bout, out, 4096, 1024, 1024);
}